// round 6
// baseline (speedup 1.0000x reference)
#include <cuda_runtime.h>
#include <math.h>

#define BH 32
#define NSEQ 8192
#define DIM 64
#define M 32
#define SCALE 0.125f
#define NCH 32

typedef unsigned long long u64;
typedef unsigned int u32;

__device__ float g_KLt[BH * DIM * M];            // [h][k][m]
__device__ float g_Bs[BH * M * M];
__device__ float g_A[(size_t)BH * NSEQ * M];     // 32 MB
__device__ float g_Yp[(size_t)BH * NCH * 2080];  // [h][ch][m*65+c] 8.5MB
__device__ float g_Y[BH * 2080];                 // [h][m][d:64 + y1]
__device__ float g_X[BH * M * 65];               // [h][m][d:64 + x1]

__device__ __forceinline__ u64 pk2(float lo, float hi) {
    u64 r; asm("mov.b64 %0, {%1, %2};" : "=l"(r) : "r"(__float_as_uint(lo)), "r"(__float_as_uint(hi))); return r;
}
__device__ __forceinline__ u64 pku(u32 lo, u32 hi) {
    u64 r; asm("mov.b64 %0, {%1, %2};" : "=l"(r) : "r"(lo), "r"(hi)); return r;
}
__device__ __forceinline__ void upk2(u64 v, float& lo, float& hi) {
    u32 a, b; asm("mov.b64 {%0, %1}, %2;" : "=r"(a), "=r"(b) : "l"(v));
    lo = __uint_as_float(a); hi = __uint_as_float(b);
}
__device__ __forceinline__ u64 ffma2(u64 a, u64 b, u64 c) {
    u64 d; asm("fma.rn.f32x2 %0, %1, %2, %3;" : "=l"(d) : "l"(a), "l"(b), "l"(c)); return d;
}

__global__ void k_nop() {}

// ---- landmarks + Bs + KLt --------------------------------------------------
__global__ void k_prep(const float* __restrict__ Q, const float* __restrict__ K) {
    int h = blockIdx.x, tid = threadIdx.x;
    __shared__ float sQL[M * 65], sKL[M * 65], sLg[M * 33], sBm[M * 33];
    for (int e = tid; e < M * DIM; e += 128) {
        int m = e >> 6, k = e & 63;
        int idx = (m * (NSEQ - 1)) / (M - 1);
        sKL[m * 65 + k] = K[((size_t)h * NSEQ + idx) * DIM + k] * SCALE;
        sQL[m * 65 + k] = Q[((size_t)h * NSEQ + idx) * DIM + k];
    }
    __syncthreads();
    for (int e = tid; e < M * DIM; e += 128) {
        int m = e & 31, k = e >> 5;
        g_KLt[(h * DIM + k) * M + m] = sKL[m * 65 + k];
    }
    for (int e = tid; e < M * M; e += 128) {
        int i = e >> 5, j = e & 31;
        float s = 0.f;
        #pragma unroll 8
        for (int k = 0; k < DIM; k++) s += sQL[i * 65 + k] * sKL[j * 65 + k];
        sLg[i * 33 + j] = s;
    }
    __syncthreads();
    if (tid < M) {
        int i = tid;
        float mx = -1e30f;
        for (int j = 0; j < M; j++) mx = fmaxf(mx, sLg[i * 33 + j]);
        float s = 0.f;
        for (int j = 0; j < M; j++) { float e2 = __expf(sLg[i * 33 + j] - mx); sBm[i * 33 + j] = e2; s += e2; }
        float r = 1.f / s;
        for (int j = 0; j < M; j++) sBm[i * 33 + j] *= r;
    }
    __syncthreads();
    for (int e = tid; e < M * M; e += 128) {
        int i = e >> 5, j = e & 31;
        g_Bs[h * M * M + e] = 0.5f * (sBm[i * 33 + j] + sBm[j * 33 + i]) + (i == j ? 1e-6f : 0.f);
    }
}

// ---- A = softmax(Q KL^T * s), 2 rows/thread, 256-row tiles -----------------
#define KA_SMEM ((256 * 65 + DIM * M) * 4)
__global__ void __launch_bounds__(128) k_A(const float* __restrict__ Q) {
    extern __shared__ float sm[];
    float* sQ = sm;
    float* sKL = sm + 256 * 65;
    const int h = blockIdx.y, tile = blockIdx.x, tid = threadIdx.x;
    for (int e = tid; e < DIM * M; e += 128) sKL[e] = g_KLt[h * DIM * M + e];
    const float4* Qg = (const float4*)(Q + ((size_t)h * NSEQ + (size_t)tile * 256) * DIM);
    for (int e4 = tid; e4 < 256 * 16; e4 += 128) {
        float4 v = Qg[e4];
        int n = e4 >> 4, k = (e4 & 15) * 4;
        float* p = sQ + n * 65 + k;
        p[0] = v.x; p[1] = v.y; p[2] = v.z; p[3] = v.w;
    }
    __syncthreads();
    u64 acc0[16], acc1[16];
    #pragma unroll
    for (int j = 0; j < 16; j++) { acc0[j] = 0ull; acc1[j] = 0ull; }
    const float* q0 = sQ + tid * 65;
    const float* q1 = sQ + (tid + 128) * 65;
    #pragma unroll 2
    for (int k = 0; k < DIM; k++) {
        float qa = q0[k], qb = q1[k];
        u64 da = pk2(qa, qa), db = pk2(qb, qb);
        const uint4* kl = (const uint4*)(sKL + k * M);
        #pragma unroll
        for (int j = 0; j < 8; j++) {
            uint4 b = kl[j];
            u64 b0 = pku(b.x, b.y), b1 = pku(b.z, b.w);
            acc0[2 * j]     = ffma2(da, b0, acc0[2 * j]);
            acc0[2 * j + 1] = ffma2(da, b1, acc0[2 * j + 1]);
            acc1[2 * j]     = ffma2(db, b0, acc1[2 * j]);
            acc1[2 * j + 1] = ffma2(db, b1, acc1[2 * j + 1]);
        }
    }
    for (int r = 0; r < 2; r++) {
        u64* acc = r ? acc1 : acc0;
        float a[32];
        #pragma unroll
        for (int j = 0; j < 16; j++) upk2(acc[j], a[2 * j], a[2 * j + 1]);
        float mx = a[0];
        #pragma unroll
        for (int j = 1; j < 32; j++) mx = fmaxf(mx, a[j]);
        float s = 0.f;
        #pragma unroll
        for (int j = 0; j < 32; j++) { a[j] = __expf(a[j] - mx); s += a[j]; }
        float rc = 1.f / s;
        float4* gA = (float4*)(g_A + ((size_t)h * NSEQ + (size_t)tile * 256 + tid + r * 128) * M);
        #pragma unroll
        for (int j = 0; j < 8; j++)
            gA[j] = make_float4(a[4 * j] * rc, a[4 * j + 1] * rc, a[4 * j + 2] * rc, a[4 * j + 3] * rc);
    }
}

// ---- Y partials: warp-per-row-stripe + in-block tree reduction -------------
__global__ void __launch_bounds__(256) k_Y(const float* __restrict__ V) {
    __shared__ float sRed[4][2048];
    __shared__ float sY1[4][32];
    const int h = blockIdx.y, ch = blockIdx.x;
    const int tid = threadIdx.x, w = tid >> 5, l = tid & 31;
    const int RPC = NSEQ / NCH;  // 256
    const float* Ab = g_A + ((size_t)h * NSEQ + (size_t)ch * RPC) * M;
    const float* Vb = V + ((size_t)h * NSEQ + (size_t)ch * RPC) * DIM;
    u64 acc[16][2], y1p[16];
    #pragma unroll
    for (int j = 0; j < 16; j++) { acc[j][0] = 0ull; acc[j][1] = 0ull; y1p[j] = 0ull; }
    const u64 ONE2 = pk2(1.f, 1.f);
    for (int r = w; r < RPC; r += 8) {
        const uint4* arow = (const uint4*)(Ab + (size_t)r * M);
        u64 vp = *(const u64*)(Vb + (size_t)r * DIM + 2 * l);
        float vlo, vhi; upk2(vp, vlo, vhi);
        u64 v0 = pk2(vlo, vlo), v1 = pk2(vhi, vhi);
        #pragma unroll
        for (int j = 0; j < 8; j++) {
            uint4 a4 = arow[j];
            u64 ap0 = pku(a4.x, a4.y), ap1 = pku(a4.z, a4.w);
            acc[2 * j][0]     = ffma2(ap0, v0, acc[2 * j][0]);
            acc[2 * j][1]     = ffma2(ap0, v1, acc[2 * j][1]);
            acc[2 * j + 1][0] = ffma2(ap1, v0, acc[2 * j + 1][0]);
            acc[2 * j + 1][1] = ffma2(ap1, v1, acc[2 * j + 1][1]);
            y1p[2 * j]     = ffma2(ap0, ONE2, y1p[2 * j]);
            y1p[2 * j + 1] = ffma2(ap1, ONE2, y1p[2 * j + 1]);
        }
    }
    // unpack: yf[mp] = {Y[2mp][2l], Y[2mp+1][2l], Y[2mp][2l+1], Y[2mp+1][2l+1]}
    float yf[16][4], y1f[16][2];
    #pragma unroll
    for (int mp = 0; mp < 16; mp++) {
        upk2(acc[mp][0], yf[mp][0], yf[mp][1]);
        upk2(acc[mp][1], yf[mp][2], yf[mp][3]);
        upk2(y1p[mp], y1f[mp][0], y1f[mp][1]);
    }
    for (int half = 4; half >= 1; half >>= 1) {
        __syncthreads();
        if (w >= half && w < 2 * half) {
            float* dst = sRed[w - half];
            #pragma unroll
            for (int mp = 0; mp < 16; mp++) {
                dst[(2 * mp) * 64 + 2 * l]         = yf[mp][0];
                dst[(2 * mp + 1) * 64 + 2 * l]     = yf[mp][1];
                dst[(2 * mp) * 64 + 2 * l + 1]     = yf[mp][2];
                dst[(2 * mp + 1) * 64 + 2 * l + 1] = yf[mp][3];
            }
            if (l == 0) {
                float* d1 = sY1[w - half];
                #pragma unroll
                for (int mp = 0; mp < 16; mp++) { d1[2 * mp] = y1f[mp][0]; d1[2 * mp + 1] = y1f[mp][1]; }
            }
        }
        __syncthreads();
        if (w < half) {
            const float* src = sRed[w];
            #pragma unroll
            for (int mp = 0; mp < 16; mp++) {
                yf[mp][0] += src[(2 * mp) * 64 + 2 * l];
                yf[mp][1] += src[(2 * mp + 1) * 64 + 2 * l];
                yf[mp][2] += src[(2 * mp) * 64 + 2 * l + 1];
                yf[mp][3] += src[(2 * mp + 1) * 64 + 2 * l + 1];
            }
            if (l == 0) {
                const float* s1 = sY1[w];
                #pragma unroll
                for (int mp = 0; mp < 16; mp++) { y1f[mp][0] += s1[2 * mp]; y1f[mp][1] += s1[2 * mp + 1]; }
            }
        }
    }
    __syncthreads();
    if (w == 0) {
        float* dst = sRed[0];
        #pragma unroll
        for (int mp = 0; mp < 16; mp++) {
            dst[(2 * mp) * 64 + 2 * l]         = yf[mp][0];
            dst[(2 * mp + 1) * 64 + 2 * l]     = yf[mp][1];
            dst[(2 * mp) * 64 + 2 * l + 1]     = yf[mp][2];
            dst[(2 * mp + 1) * 64 + 2 * l + 1] = yf[mp][3];
        }
        if (l == 0) {
            #pragma unroll
            for (int mp = 0; mp < 16; mp++) { sY1[0][2 * mp] = y1f[mp][0]; sY1[0][2 * mp + 1] = y1f[mp][1]; }
        }
    }
    __syncthreads();
    float* yp = g_Yp + ((size_t)(h * NCH + ch)) * 2080;
    for (int e = tid; e < 2080; e += 256) {
        int m = e / 65, c = e % 65;
        yp[e] = (c < 64) ? sRed[0][m * 64 + c] : sY1[0][m];
    }
}

// ---- reduce NCH partials, coalesced ----------------------------------------
__global__ void __launch_bounds__(1024) k_red() {
    int h = blockIdx.y;
    int e = blockIdx.x * 1024 + threadIdx.x;
    if (e >= 2080) return;
    const float* base = g_Yp + (size_t)h * NCH * 2080;
    float s = 0.f;
    #pragma unroll 8
    for (int c2 = 0; c2 < NCH; c2++) s += base[(size_t)c2 * 2080 + e];
    g_Y[h * 2080 + e] = s;
}

// ---- pivoted Gauss-Jordan, warp pivot search -------------------------------
__global__ void __launch_bounds__(128) k_solve() {
    const int h = blockIdx.x, c = threadIdx.x;
    __shared__ float sx[M * 97];
    __shared__ float sf[M];
    __shared__ int sp;
    if (c < M) {
        for (int i = 0; i < M; i++) sx[i * 97 + c] = g_Bs[h * M * M + i * M + c];
    } else if (c < 97) {
        int d = c - 32;
        for (int i = 0; i < M; i++) sx[i * 97 + c] = g_Y[h * 2080 + i * 65 + d];
    }
    __syncthreads();
    for (int k = 0; k < M; k++) {
        if (c < 32) {
            float v = (c >= k) ? fabsf(sx[c * 97 + k]) : -1.f;
            int bi = c;
            #pragma unroll
            for (int o = 16; o; o >>= 1) {
                float ov = __shfl_xor_sync(~0u, v, o);
                int oi = __shfl_xor_sync(~0u, bi, o);
                if (ov > v) { v = ov; bi = oi; }
            }
            if (c == 0) sp = bi;
        }
        __syncthreads();
        int p = sp;
        if (c < 97 && p != k) {
            float t = sx[k * 97 + c]; sx[k * 97 + c] = sx[p * 97 + c]; sx[p * 97 + c] = t;
        }
        __syncthreads();
        if (c < 32) sf[c] = sx[c * 97 + k];
        __syncthreads();
        if (c < 97) {
            float inv = 1.f / sf[k];
            float xk = sx[k * 97 + c] * inv;
            sx[k * 97 + c] = xk;
            #pragma unroll
            for (int i = 0; i < M; i++) {
                if (i == k) continue;
                sx[i * 97 + c] = fmaf(-sf[i], xk, sx[i * 97 + c]);
            }
        }
        __syncthreads();
    }
    if (c >= 32 && c < 97) {
        for (int i = 0; i < M; i++)
            g_X[(h * M + i) * 65 + (c - 32)] = sx[i * 97 + c];
    }
}

// ---- out = (A X) / max(A x1, 1e-20): 1 row x 32 cols per thread ------------
__global__ void __launch_bounds__(256) k_pass2(float* __restrict__ out) {
    __shared__ float sX[M * 68];
    __shared__ float sA[128 * 33];
    const int h = blockIdx.y, blk = blockIdx.x, tid = threadIdx.x;
    for (int e = tid; e < M * 65; e += 256) {
        int m = e / 65, d = e % 65;
        sX[m * 68 + d] = g_X[h * M * 65 + e];
    }
    const float4* Ag = (const float4*)(g_A + ((size_t)h * NSEQ + (size_t)blk * 128) * M);
    for (int e4 = tid; e4 < 128 * 8; e4 += 256) {
        float4 v = Ag[e4];
        int rr = e4 >> 3, cc = (e4 & 7) * 4;
        float* p = sA + rr * 33 + cc;
        p[0] = v.x; p[1] = v.y; p[2] = v.z; p[3] = v.w;
    }
    __syncthreads();
    const int row = tid >> 1, half = tid & 1;
    u64 acc[16];
    #pragma unroll
    for (int j = 0; j < 16; j++) acc[j] = 0ull;
    float den = 0.f;
    const float* ap = sA + row * 33;
    const float* xh = sX + 32 * half;
    #pragma unroll 2
    for (int m = 0; m < M; m++) {
        float av = ap[m];
        den = fmaf(av, sX[m * 68 + 64], den);
        u64 ad = pk2(av, av);
        const uint4* xr = (const uint4*)(xh + m * 68);
        #pragma unroll
        for (int j = 0; j < 8; j++) {
            uint4 b = xr[j];
            acc[2 * j]     = ffma2(ad, pku(b.x, b.y), acc[2 * j]);
            acc[2 * j + 1] = ffma2(ad, pku(b.z, b.w), acc[2 * j + 1]);
        }
    }
    float rinv = 1.f / fmaxf(den, 1e-20f);
    float4* op = (float4*)(out + ((size_t)h * NSEQ + (size_t)blk * 128 + row) * DIM + 32 * half);
    #pragma unroll
    for (int j = 0; j < 8; j++) {
        float f0, f1, f2, f3;
        upk2(acc[2 * j], f0, f1);
        upk2(acc[2 * j + 1], f2, f3);
        op[j] = make_float4(f0 * rinv, f1 * rinv, f2 * rinv, f3 * rinv);
    }
}

extern "C" void kernel_launch(void* const* d_in, const int* in_sizes, int n_in,
                              void* d_out, int out_size) {
    const float* Q = (const float*)d_in[0];
    const float* K = (const float*)d_in[1];
    const float* V = (const float*)d_in[2];
    float* out = (float*)d_out;
    cudaFuncSetAttribute(k_A, cudaFuncAttributeMaxDynamicSharedMemorySize, KA_SMEM);
    k_prep<<<BH, 128>>>(Q, K);
    k_nop<<<1, 32>>>();
    k_nop<<<1, 32>>>();
    k_A<<<dim3(NSEQ / 256, BH), 128, KA_SMEM>>>(Q);   // launch #4 -> profiled
    k_Y<<<dim3(NCH, BH), 256>>>(V);
    k_red<<<dim3(3, BH), 1024>>>();
    k_solve<<<BH, 128>>>();
    k_pass2<<<dim3(NSEQ / 128, BH), 256>>>(out);
}

// round 7
// speedup vs baseline: 1.0898x; 1.0898x over previous
#include <cuda_runtime.h>
#include <math.h>

#define BH 32
#define NSEQ 8192
#define DIM 64
#define M 32
#define SCALE 0.125f
#define NCH 32

typedef unsigned long long u64;
typedef unsigned int u32;

__device__ float g_KLt[BH * DIM * M];            // [h][k][m]
__device__ float g_Bs[BH * M * M];
__device__ float g_A[(size_t)BH * NSEQ * M];     // 32 MB
__device__ float g_Yp[(size_t)BH * NCH * 2080];  // [h][ch][m*65+c] 8.5MB
__device__ float g_Y[BH * 2080];
__device__ float g_X[BH * M * 65];

__device__ __forceinline__ u64 pk2(float lo, float hi) {
    u64 r; asm("mov.b64 %0, {%1, %2};" : "=l"(r) : "r"(__float_as_uint(lo)), "r"(__float_as_uint(hi))); return r;
}
__device__ __forceinline__ u64 pku(u32 lo, u32 hi) {
    u64 r; asm("mov.b64 %0, {%1, %2};" : "=l"(r) : "r"(lo), "r"(hi)); return r;
}
__device__ __forceinline__ void upk2(u64 v, float& lo, float& hi) {
    u32 a, b; asm("mov.b64 {%0, %1}, %2;" : "=r"(a), "=r"(b) : "l"(v));
    lo = __uint_as_float(a); hi = __uint_as_float(b);
}
__device__ __forceinline__ u64 ffma2(u64 a, u64 b, u64 c) {
    u64 d; asm("fma.rn.f32x2 %0, %1, %2, %3;" : "=l"(d) : "l"(a), "l"(b), "l"(c)); return d;
}

__global__ void k_nop() {}

// ---- landmarks + Bs + KLt --------------------------------------------------
__global__ void k_prep(const float* __restrict__ Q, const float* __restrict__ K) {
    int h = blockIdx.x, tid = threadIdx.x;
    __shared__ float sQL[M * 65], sKL[M * 65], sLg[M * 33], sBm[M * 33];
    for (int e = tid; e < M * DIM; e += 128) {
        int m = e >> 6, k = e & 63;
        int idx = (m * (NSEQ - 1)) / (M - 1);
        sKL[m * 65 + k] = K[((size_t)h * NSEQ + idx) * DIM + k] * SCALE;
        sQL[m * 65 + k] = Q[((size_t)h * NSEQ + idx) * DIM + k];
    }
    __syncthreads();
    for (int e = tid; e < M * DIM; e += 128) {
        int m = e & 31, k = e >> 5;
        g_KLt[(h * DIM + k) * M + m] = sKL[m * 65 + k];
    }
    for (int e = tid; e < M * M; e += 128) {
        int i = e >> 5, j = e & 31;
        float s = 0.f;
        #pragma unroll 8
        for (int k = 0; k < DIM; k++) s += sQL[i * 65 + k] * sKL[j * 65 + k];
        sLg[i * 33 + j] = s;
    }
    __syncthreads();
    if (tid < M) {
        int i = tid;
        float mx = -1e30f;
        for (int j = 0; j < M; j++) mx = fmaxf(mx, sLg[i * 33 + j]);
        float s = 0.f;
        for (int j = 0; j < M; j++) { float e2 = __expf(sLg[i * 33 + j] - mx); sBm[i * 33 + j] = e2; s += e2; }
        float r = 1.f / s;
        for (int j = 0; j < M; j++) sBm[i * 33 + j] *= r;
    }
    __syncthreads();
    for (int e = tid; e < M * M; e += 128) {
        int i = e >> 5, j = e & 31;
        g_Bs[h * M * M + e] = 0.5f * (sBm[i * 33 + j] + sBm[j * 33 + i]) + (i == j ? 1e-6f : 0.f);
    }
}

// ---- A = softmax(Q KL^T * s): 1 row/thread, 128-row tiles, 5 blocks/SM -----
__global__ void __launch_bounds__(128, 5) k_A(const float* __restrict__ Q) {
    __shared__ __align__(16) float sQ[128 * 65];   // reused as stride-36 A tile
    __shared__ __align__(16) float sKL[DIM * M];
    const int h = blockIdx.y, tile = blockIdx.x, tid = threadIdx.x;
    for (int e = tid; e < DIM * M; e += 128) sKL[e] = g_KLt[h * DIM * M + e];
    const float4* Qg = (const float4*)(Q + ((size_t)h * NSEQ + (size_t)tile * 128) * DIM);
    for (int e4 = tid; e4 < 128 * 16; e4 += 128) {
        float4 v = Qg[e4];
        int n = e4 >> 4, k = (e4 & 15) * 4;
        float* p = sQ + n * 65 + k;
        p[0] = v.x; p[1] = v.y; p[2] = v.z; p[3] = v.w;
    }
    __syncthreads();
    u64 acc[16];
    #pragma unroll
    for (int j = 0; j < 16; j++) acc[j] = 0ull;
    const float* q = sQ + tid * 65;
    #pragma unroll 2
    for (int k = 0; k < DIM; k++) {
        float qv = q[k];
        u64 qd = pk2(qv, qv);
        const uint4* kl = (const uint4*)(sKL + k * M);
        #pragma unroll
        for (int j = 0; j < 8; j++) {
            uint4 b = kl[j];
            acc[2 * j]     = ffma2(qd, pku(b.x, b.y), acc[2 * j]);
            acc[2 * j + 1] = ffma2(qd, pku(b.z, b.w), acc[2 * j + 1]);
        }
    }
    float a[32];
    #pragma unroll
    for (int j = 0; j < 16; j++) upk2(acc[j], a[2 * j], a[2 * j + 1]);
    float mx = a[0];
    #pragma unroll
    for (int j = 1; j < 32; j++) mx = fmaxf(mx, a[j]);
    float s = 0.f;
    #pragma unroll
    for (int j = 0; j < 32; j++) { a[j] = __expf(a[j] - mx); s += a[j]; }
    float rc = 1.f / s;
    __syncthreads();                 // done reading sQ
    float4* sA4 = (float4*)(sQ + tid * 36);
    #pragma unroll
    for (int j = 0; j < 8; j++)
        sA4[j] = make_float4(a[4 * j] * rc, a[4 * j + 1] * rc, a[4 * j + 2] * rc, a[4 * j + 3] * rc);
    __syncthreads();
    float4* gA4 = (float4*)(g_A + ((size_t)h * NSEQ + (size_t)tile * 128) * M);
    for (int e4 = tid; e4 < 1024; e4 += 128) {
        int row = e4 >> 3, c4 = e4 & 7;
        gA4[e4] = *(const float4*)(sQ + row * 36 + c4 * 4);   // coalesced
    }
}

// ---- Y partials: 4 warps, single-stage reduce, y1 via coalesced LDG --------
__global__ void __launch_bounds__(128, 5) k_Y(const float* __restrict__ V) {
    __shared__ float sRed[4][2048];
    __shared__ float sY1[4][32];
    const int h = blockIdx.y, ch = blockIdx.x;
    const int tid = threadIdx.x, w = tid >> 5, l = tid & 31;
    const int RPC = NSEQ / NCH;  // 256
    const float* Ab = g_A + ((size_t)h * NSEQ + (size_t)ch * RPC) * M;
    const float* Vb = V + ((size_t)h * NSEQ + (size_t)ch * RPC) * DIM;
    u64 acc[16][2];
    #pragma unroll
    for (int j = 0; j < 16; j++) { acc[j][0] = 0ull; acc[j][1] = 0ull; }
    float y1 = 0.f;
    #pragma unroll 2
    for (int r = w; r < RPC; r += 4) {
        const uint4* arow = (const uint4*)(Ab + (size_t)r * M);
        y1 += Ab[(size_t)r * M + l];
        u64 vp = *(const u64*)(Vb + (size_t)r * DIM + 2 * l);
        float vlo, vhi; upk2(vp, vlo, vhi);
        u64 v0 = pk2(vlo, vlo), v1 = pk2(vhi, vhi);
        #pragma unroll
        for (int j = 0; j < 8; j++) {
            uint4 a4 = arow[j];
            u64 ap0 = pku(a4.x, a4.y), ap1 = pku(a4.z, a4.w);
            acc[2 * j][0]     = ffma2(ap0, v0, acc[2 * j][0]);
            acc[2 * j][1]     = ffma2(ap0, v1, acc[2 * j][1]);
            acc[2 * j + 1][0] = ffma2(ap1, v0, acc[2 * j + 1][0]);
            acc[2 * j + 1][1] = ffma2(ap1, v1, acc[2 * j + 1][1]);
        }
    }
    float* dst = sRed[w];
    #pragma unroll
    for (int mp = 0; mp < 16; mp++) {
        float f0, f1, f2, f3;
        upk2(acc[mp][0], f0, f1);
        upk2(acc[mp][1], f2, f3);
        dst[(2 * mp) * 64 + 2 * l]         = f0;
        dst[(2 * mp + 1) * 64 + 2 * l]     = f1;
        dst[(2 * mp) * 64 + 2 * l + 1]     = f2;
        dst[(2 * mp + 1) * 64 + 2 * l + 1] = f3;
    }
    sY1[w][l] = y1;
    __syncthreads();
    float* yp = g_Yp + ((size_t)(h * NCH + ch)) * 2080;
    for (int e = tid; e < 2080; e += 128) {
        int m = e / 65, c = e % 65;
        float s2 = (c < 64)
            ? (sRed[0][m * 64 + c] + sRed[1][m * 64 + c] + sRed[2][m * 64 + c] + sRed[3][m * 64 + c])
            : (sY1[0][m] + sY1[1][m] + sY1[2][m] + sY1[3][m]);
        yp[e] = s2;
    }
}

// ---- reduce NCH partials, coalesced ----------------------------------------
__global__ void __launch_bounds__(1024) k_red() {
    int h = blockIdx.y;
    int e = blockIdx.x * 1024 + threadIdx.x;
    if (e >= 2080) return;
    const float* base = g_Yp + (size_t)h * NCH * 2080;
    float s = 0.f;
    #pragma unroll 8
    for (int c2 = 0; c2 < NCH; c2++) s += base[(size_t)c2 * 2080 + e];
    g_Y[h * 2080 + e] = s;
}

// ---- pivoted Gauss-Jordan, warp pivot search -------------------------------
__global__ void __launch_bounds__(128) k_solve() {
    const int h = blockIdx.x, c = threadIdx.x;
    __shared__ float sx[M * 97];
    __shared__ float sf[M];
    __shared__ int sp;
    if (c < M) {
        for (int i = 0; i < M; i++) sx[i * 97 + c] = g_Bs[h * M * M + i * M + c];
    } else if (c < 97) {
        int d = c - 32;
        for (int i = 0; i < M; i++) sx[i * 97 + c] = g_Y[h * 2080 + i * 65 + d];
    }
    __syncthreads();
    for (int k = 0; k < M; k++) {
        if (c < 32) {
            float v = (c >= k) ? fabsf(sx[c * 97 + k]) : -1.f;
            int bi = c;
            #pragma unroll
            for (int o = 16; o; o >>= 1) {
                float ov = __shfl_xor_sync(~0u, v, o);
                int oi = __shfl_xor_sync(~0u, bi, o);
                if (ov > v) { v = ov; bi = oi; }
            }
            if (c == 0) sp = bi;
        }
        __syncthreads();
        int p = sp;
        if (c < 97 && p != k) {
            float t = sx[k * 97 + c]; sx[k * 97 + c] = sx[p * 97 + c]; sx[p * 97 + c] = t;
        }
        __syncthreads();
        if (c < 32) sf[c] = sx[c * 97 + k];
        __syncthreads();
        if (c < 97) {
            float inv = 1.f / sf[k];
            float xk = sx[k * 97 + c] * inv;
            sx[k * 97 + c] = xk;
            #pragma unroll
            for (int i = 0; i < M; i++) {
                if (i == k) continue;
                sx[i * 97 + c] = fmaf(-sf[i], xk, sx[i * 97 + c]);
            }
        }
        __syncthreads();
    }
    if (c >= 32 && c < 97) {
        for (int i = 0; i < M; i++)
            g_X[(h * M + i) * 65 + (c - 32)] = sx[i * 97 + c];
    }
}

// ---- out = (A X) / max(A x1, 1e-20): 1 row x 32 cols per thread ------------
__global__ void __launch_bounds__(256) k_pass2(float* __restrict__ out) {
    __shared__ float sX[M * 68];
    __shared__ float sA[128 * 33];
    const int h = blockIdx.y, blk = blockIdx.x, tid = threadIdx.x;
    for (int e = tid; e < M * 65; e += 256) {
        int m = e / 65, d = e % 65;
        sX[m * 68 + d] = g_X[h * M * 65 + e];
    }
    const float4* Ag = (const float4*)(g_A + ((size_t)h * NSEQ + (size_t)blk * 128) * M);
    for (int e4 = tid; e4 < 128 * 8; e4 += 256) {
        float4 v = Ag[e4];
        int rr = e4 >> 3, cc = (e4 & 7) * 4;
        float* p = sA + rr * 33 + cc;
        p[0] = v.x; p[1] = v.y; p[2] = v.z; p[3] = v.w;
    }
    __syncthreads();
    const int row = tid >> 1, half = tid & 1;
    u64 acc[16];
    #pragma unroll
    for (int j = 0; j < 16; j++) acc[j] = 0ull;
    float den = 0.f;
    const float* ap = sA + row * 33;
    const float* xh = sX + 32 * half;
    #pragma unroll 2
    for (int m = 0; m < M; m++) {
        float av = ap[m];
        den = fmaf(av, sX[m * 68 + 64], den);
        u64 ad = pk2(av, av);
        const uint4* xr = (const uint4*)(xh + m * 68);
        #pragma unroll
        for (int j = 0; j < 8; j++) {
            uint4 b = xr[j];
            acc[2 * j]     = ffma2(ad, pku(b.x, b.y), acc[2 * j]);
            acc[2 * j + 1] = ffma2(ad, pku(b.z, b.w), acc[2 * j + 1]);
        }
    }
    float rinv = 1.f / fmaxf(den, 1e-20f);
    float4* op = (float4*)(out + ((size_t)h * NSEQ + (size_t)blk * 128 + row) * DIM + 32 * half);
    #pragma unroll
    for (int j = 0; j < 8; j++) {
        float f0, f1, f2, f3;
        upk2(acc[2 * j], f0, f1);
        upk2(acc[2 * j + 1], f2, f3);
        op[j] = make_float4(f0 * rinv, f1 * rinv, f2 * rinv, f3 * rinv);
    }
}

extern "C" void kernel_launch(void* const* d_in, const int* in_sizes, int n_in,
                              void* d_out, int out_size) {
    const float* Q = (const float*)d_in[0];
    const float* K = (const float*)d_in[1];
    const float* V = (const float*)d_in[2];
    float* out = (float*)d_out;
    k_prep<<<BH, 128>>>(Q, K);
    k_nop<<<1, 32>>>();
    k_nop<<<1, 32>>>();
    k_A<<<dim3(NSEQ / 128, BH), 128>>>(Q);   // launch #4 -> profiled
    k_Y<<<dim3(NCH, BH), 128>>>(V);
    k_red<<<dim3(3, BH), 1024>>>();
    k_solve<<<BH, 128>>>();
    k_pass2<<<dim3(NSEQ / 128, BH), 256>>>(out);
}

// round 9
// speedup vs baseline: 1.3247x; 1.2155x over previous
#include <cuda_runtime.h>
#include <math.h>

#define BH 32
#define NSEQ 8192
#define DIM 64
#define M 32
#define SCALE 0.125f
#define NCH 64

typedef unsigned long long u64;
typedef unsigned int u32;

__device__ float g_KLt[BH * DIM * M];            // [h][k][m]
__device__ float g_Bs[BH * M * M];
__device__ float g_A[(size_t)BH * NSEQ * M];     // 32 MB
__device__ float g_Yp[(size_t)BH * NCH * 2080];  // 17 MB
__device__ float g_Y[BH * 2080];
__device__ float g_X[BH * M * 65];

__device__ __forceinline__ u64 pk2(float lo, float hi) {
    u64 r; asm("mov.b64 %0, {%1, %2};" : "=l"(r) : "r"(__float_as_uint(lo)), "r"(__float_as_uint(hi))); return r;
}
__device__ __forceinline__ u64 pku(u32 lo, u32 hi) {
    u64 r; asm("mov.b64 %0, {%1, %2};" : "=l"(r) : "r"(lo), "r"(hi)); return r;
}
__device__ __forceinline__ void upk2(u64 v, float& lo, float& hi) {
    u32 a, b; asm("mov.b64 {%0, %1}, %2;" : "=r"(a), "=r"(b) : "l"(v));
    lo = __uint_as_float(a); hi = __uint_as_float(b);
}
__device__ __forceinline__ u64 ffma2(u64 a, u64 b, u64 c) {
    u64 d; asm("fma.rn.f32x2 %0, %1, %2, %3;" : "=l"(d) : "l"(a), "l"(b), "l"(c)); return d;
}

__global__ void k_nop() {}

// ---- landmarks + Bs + KLt --------------------------------------------------
__global__ void k_prep(const float* __restrict__ Q, const float* __restrict__ K) {
    int h = blockIdx.x, tid = threadIdx.x;
    __shared__ float sQL[M * 65], sKL[M * 65], sLg[M * 33], sBm[M * 33];
    for (int e = tid; e < M * DIM; e += 128) {
        int m = e >> 6, k = e & 63;
        int idx = (m * (NSEQ - 1)) / (M - 1);
        sKL[m * 65 + k] = K[((size_t)h * NSEQ + idx) * DIM + k] * SCALE;
        sQL[m * 65 + k] = Q[((size_t)h * NSEQ + idx) * DIM + k];
    }
    __syncthreads();
    for (int e = tid; e < M * DIM; e += 128) {
        int m = e & 31, k = e >> 5;
        g_KLt[(h * DIM + k) * M + m] = sKL[m * 65 + k];
    }
    for (int e = tid; e < M * M; e += 128) {
        int i = e >> 5, j = e & 31;
        float s = 0.f;
        #pragma unroll 8
        for (int k = 0; k < DIM; k++) s += sQL[i * 65 + k] * sKL[j * 65 + k];
        sLg[i * 33 + j] = s;
    }
    __syncthreads();
    if (tid < M) {
        int i = tid;
        float mx = -1e30f;
        for (int j = 0; j < M; j++) mx = fmaxf(mx, sLg[i * 33 + j]);
        float s = 0.f;
        for (int j = 0; j < M; j++) { float e2 = __expf(sLg[i * 33 + j] - mx); sBm[i * 33 + j] = e2; s += e2; }
        float r = 1.f / s;
        for (int j = 0; j < M; j++) sBm[i * 33 + j] *= r;
    }
    __syncthreads();
    for (int e = tid; e < M * M; e += 128) {
        int i = e >> 5, j = e & 31;
        g_Bs[h * M * M + e] = 0.5f * (sBm[i * 33 + j] + sBm[j * 33 + i]) + (i == j ? 1e-6f : 0.f);
    }
}

// ---- A = softmax(Q KL^T * s), 2 rows/thread, 256-row tiles -----------------
#define KA_SMEM ((256 * 65 + DIM * M) * 4)
__global__ void __launch_bounds__(128) k_A(const float* __restrict__ Q) {
    extern __shared__ float sm[];
    float* sQ = sm;
    float* sKL = sm + 256 * 65;
    const int h = blockIdx.y, tile = blockIdx.x, tid = threadIdx.x;
    for (int e = tid; e < DIM * M; e += 128) sKL[e] = g_KLt[h * DIM * M + e];
    const float4* Qg = (const float4*)(Q + ((size_t)h * NSEQ + (size_t)tile * 256) * DIM);
    for (int e4 = tid; e4 < 256 * 16; e4 += 128) {
        float4 v = Qg[e4];
        int n = e4 >> 4, k = (e4 & 15) * 4;
        float* p = sQ + n * 65 + k;
        p[0] = v.x; p[1] = v.y; p[2] = v.z; p[3] = v.w;
    }
    __syncthreads();
    u64 acc0[16], acc1[16];
    #pragma unroll
    for (int j = 0; j < 16; j++) { acc0[j] = 0ull; acc1[j] = 0ull; }
    const float* q0 = sQ + tid * 65;
    const float* q1 = sQ + (tid + 128) * 65;
    #pragma unroll 2
    for (int k = 0; k < DIM; k++) {
        float qa = q0[k], qb = q1[k];
        u64 da = pk2(qa, qa), db = pk2(qb, qb);
        const uint4* kl = (const uint4*)(sKL + k * M);
        #pragma unroll
        for (int j = 0; j < 8; j++) {
            uint4 b = kl[j];
            u64 b0 = pku(b.x, b.y), b1 = pku(b.z, b.w);
            acc0[2 * j]     = ffma2(da, b0, acc0[2 * j]);
            acc0[2 * j + 1] = ffma2(da, b1, acc0[2 * j + 1]);
            acc1[2 * j]     = ffma2(db, b0, acc1[2 * j]);
            acc1[2 * j + 1] = ffma2(db, b1, acc1[2 * j + 1]);
        }
    }
    for (int r = 0; r < 2; r++) {
        u64* acc = r ? acc1 : acc0;
        float a[32];
        #pragma unroll
        for (int j = 0; j < 16; j++) upk2(acc[j], a[2 * j], a[2 * j + 1]);
        float mx = a[0];
        #pragma unroll
        for (int j = 1; j < 32; j++) mx = fmaxf(mx, a[j]);
        float s = 0.f;
        #pragma unroll
        for (int j = 0; j < 32; j++) { a[j] = __expf(a[j] - mx); s += a[j]; }
        float rc = 1.f / s;
        float4* gA = (float4*)(g_A + ((size_t)h * NSEQ + (size_t)tile * 256 + tid + r * 128) * M);
        #pragma unroll
        for (int j = 0; j < 8; j++)
            gA[j] = make_float4(a[4 * j] * rc, a[4 * j + 1] * rc, a[4 * j + 2] * rc, a[4 * j + 3] * rc);
    }
}

// ---- Y partials: smem-staged A+V tiles, 128 rows, 4 warps ------------------
#define SV_STR 68
__global__ void __launch_bounds__(128) k_Y(const float* __restrict__ V) {
    __shared__ __align__(16) float sA[128 * 36];     // 18.4 KB
    __shared__ __align__(16) float sV[128 * SV_STR]; // 34.8 KB (reused for reduce)
    const int h = blockIdx.y, ch = blockIdx.x;
    const int tid = threadIdx.x, w = tid >> 5, l = tid & 31;
    const float4* Ag = (const float4*)(g_A + ((size_t)h * NSEQ + (size_t)ch * 128) * M);
    for (int e4 = tid; e4 < 128 * 8; e4 += 128) {
        int row = e4 >> 3, c4 = e4 & 7;
        *(float4*)(sA + row * 36 + c4 * 4) = Ag[e4];
    }
    const float4* Vg = (const float4*)(V + ((size_t)h * NSEQ + (size_t)ch * 128) * DIM);
    for (int e4 = tid; e4 < 128 * 16; e4 += 128) {
        int row = e4 >> 4, c4 = e4 & 15;
        *(float4*)(sV + row * SV_STR + c4 * 4) = Vg[e4];
    }
    __syncthreads();
    u64 acc[16][2];
    #pragma unroll
    for (int j = 0; j < 16; j++) { acc[j][0] = 0ull; acc[j][1] = 0ull; }
    float y1 = 0.f;
    for (int r = w * 32; r < w * 32 + 32; r++) {
        y1 += sA[r * 36 + l];
        u64 vp = *(const u64*)(sV + r * SV_STR + 2 * l);
        float vlo, vhi; upk2(vp, vlo, vhi);
        u64 v0 = pk2(vlo, vlo), v1 = pk2(vhi, vhi);
        const uint4* arow = (const uint4*)(sA + r * 36);
        #pragma unroll
        for (int j = 0; j < 8; j++) {
            uint4 a4 = arow[j];
            u64 ap0 = pku(a4.x, a4.y), ap1 = pku(a4.z, a4.w);
            acc[2 * j][0]     = ffma2(ap0, v0, acc[2 * j][0]);
            acc[2 * j][1]     = ffma2(ap0, v1, acc[2 * j][1]);
            acc[2 * j + 1][0] = ffma2(ap1, v0, acc[2 * j + 1][0]);
            acc[2 * j + 1][1] = ffma2(ap1, v1, acc[2 * j + 1][1]);
        }
    }
    __syncthreads();              // done reading tiles; reuse sV as 4 x 2080 slices
    float* dst = sV + w * 2080;
    #pragma unroll
    for (int mp = 0; mp < 16; mp++) {
        float f0, f1, f2, f3;
        upk2(acc[mp][0], f0, f1);
        upk2(acc[mp][1], f2, f3);
        dst[(2 * mp) * 64 + 2 * l]         = f0;
        dst[(2 * mp + 1) * 64 + 2 * l]     = f1;
        dst[(2 * mp) * 64 + 2 * l + 1]     = f2;
        dst[(2 * mp + 1) * 64 + 2 * l + 1] = f3;
    }
    dst[2048 + l] = y1;
    __syncthreads();
    float* yp = g_Yp + ((size_t)(h * NCH + ch)) * 2080;
    for (int e = tid; e < 2080; e += 128) {
        int m = e / 65, c = e % 65;
        int o = (c < 64) ? (m * 64 + c) : (2048 + m);
        yp[e] = sV[o] + sV[2080 + o] + sV[2 * 2080 + o] + sV[3 * 2080 + o];
    }
}

// ---- reduce NCH partials, coalesced ----------------------------------------
__global__ void __launch_bounds__(1024) k_red() {
    int h = blockIdx.y;
    int e = blockIdx.x * 1024 + threadIdx.x;
    if (e >= 2080) return;
    const float* base = g_Yp + (size_t)h * NCH * 2080;
    float s = 0.f;
    #pragma unroll 8
    for (int c2 = 0; c2 < NCH; c2++) s += base[(size_t)c2 * 2080 + e];
    g_Y[h * 2080 + e] = s;
}

// ---- pivoted Gauss-Jordan, warp pivot search -------------------------------
__global__ void __launch_bounds__(128) k_solve() {
    const int h = blockIdx.x, c = threadIdx.x;
    __shared__ float sx[M * 97];
    __shared__ float sf[M];
    __shared__ int sp;
    if (c < M) {
        for (int i = 0; i < M; i++) sx[i * 97 + c] = g_Bs[h * M * M + i * M + c];
    } else if (c < 97) {
        int d = c - 32;
        for (int i = 0; i < M; i++) sx[i * 97 + c] = g_Y[h * 2080 + i * 65 + d];
    }
    __syncthreads();
    for (int k = 0; k < M; k++) {
        if (c < 32) {
            float v = (c >= k) ? fabsf(sx[c * 97 + k]) : -1.f;
            int bi = c;
            #pragma unroll
            for (int o = 16; o; o >>= 1) {
                float ov = __shfl_xor_sync(~0u, v, o);
                int oi = __shfl_xor_sync(~0u, bi, o);
                if (ov > v) { v = ov; bi = oi; }
            }
            if (c == 0) sp = bi;
        }
        __syncthreads();
        int p = sp;
        if (c < 97 && p != k) {
            float t = sx[k * 97 + c]; sx[k * 97 + c] = sx[p * 97 + c]; sx[p * 97 + c] = t;
        }
        __syncthreads();
        if (c < 32) sf[c] = sx[c * 97 + k];
        __syncthreads();
        if (c < 97) {
            float inv = 1.f / sf[k];
            float xk = sx[k * 97 + c] * inv;
            sx[k * 97 + c] = xk;
            #pragma unroll
            for (int i = 0; i < M; i++) {
                if (i == k) continue;
                sx[i * 97 + c] = fmaf(-sf[i], xk, sx[i * 97 + c]);
            }
        }
        __syncthreads();
    }
    if (c >= 32 && c < 97) {
        for (int i = 0; i < M; i++)
            g_X[(h * M + i) * 65 + (c - 32)] = sx[i * 97 + c];
    }
}

// ---- out = (A X) / max(A x1, 1e-20): 1 row x 32 cols per thread ------------
__global__ void __launch_bounds__(256) k_pass2(float* __restrict__ out) {
    __shared__ float sX[M * 68];
    __shared__ float sA[128 * 33];
    const int h = blockIdx.y, blk = blockIdx.x, tid = threadIdx.x;
    for (int e = tid; e < M * 65; e += 256) {
        int m = e / 65, d = e % 65;
        sX[m * 68 + d] = g_X[h * M * 65 + e];
    }
    const float4* Ag = (const float4*)(g_A + ((size_t)h * NSEQ + (size_t)blk * 128) * M);
    for (int e4 = tid; e4 < 128 * 8; e4 += 256) {
        float4 v = Ag[e4];
        int rr = e4 >> 3, cc = (e4 & 7) * 4;
        float* p = sA + rr * 33 + cc;
        p[0] = v.x; p[1] = v.y; p[2] = v.z; p[3] = v.w;
    }
    __syncthreads();
    const int row = tid >> 1, half = tid & 1;
    u64 acc[16];
    #pragma unroll
    for (int j = 0; j < 16; j++) acc[j] = 0ull;
    float den = 0.f;
    const float* ap = sA + row * 33;
    const float* xh = sX + 32 * half;
    #pragma unroll 2
    for (int m = 0; m < M; m++) {
        float av = ap[m];
        den = fmaf(av, sX[m * 68 + 64], den);
        u64 ad = pk2(av, av);
        const uint4* xr = (const uint4*)(xh + m * 68);
        #pragma unroll
        for (int j = 0; j < 8; j++) {
            uint4 b = xr[j];
            acc[2 * j]     = ffma2(ad, pku(b.x, b.y), acc[2 * j]);
            acc[2 * j + 1] = ffma2(ad, pku(b.z, b.w), acc[2 * j + 1]);
        }
    }
    float rinv = 1.f / fmaxf(den, 1e-20f);
    float4* op = (float4*)(out + ((size_t)h * NSEQ + (size_t)blk * 128 + row) * DIM + 32 * half);
    #pragma unroll
    for (int j = 0; j < 8; j++) {
        float f0, f1, f2, f3;
        upk2(acc[2 * j], f0, f1);
        upk2(acc[2 * j + 1], f2, f3);
        op[j] = make_float4(f0 * rinv, f1 * rinv, f2 * rinv, f3 * rinv);
    }
}

extern "C" void kernel_launch(void* const* d_in, const int* in_sizes, int n_in,
                              void* d_out, int out_size) {
    const float* Q = (const float*)d_in[0];
    const float* K = (const float*)d_in[1];
    const float* V = (const float*)d_in[2];
    float* out = (float*)d_out;
    cudaFuncSetAttribute(k_A, cudaFuncAttributeMaxDynamicSharedMemorySize, KA_SMEM);
    k_prep<<<BH, 128>>>(Q, K);
    k_A<<<dim3(NSEQ / 256, BH), 128, KA_SMEM>>>(Q);
    k_nop<<<1, 32>>>();
    k_Y<<<dim3(NCH, BH), 128>>>(V);   // launch #4 -> profiled
    k_red<<<dim3(3, BH), 1024>>>();
    k_solve<<<BH, 128>>>();
    k_pass2<<<dim3(NSEQ / 128, BH), 256>>>(out);
}